// round 4
// baseline (speedup 1.0000x reference)
#include <cuda_runtime.h>
#include <cstdint>
#include <cstddef>

// Problem constants
#define Bb 64
#define Nt 577
#define Cc 768
#define Hh 12
#define SCv 0.125f
#define SPLITS 9
#define CHUNK 66        // 9*66 = 594 >= 577; 66 divisible by G=3
#define G 3             // tokens per group in k_attn

// ---------------- scratch (device globals; no allocation) ----------------
__device__ __align__(16) float g_qpart[12][Bb][Cc];            // q partial sums (kc,b,j)
__device__ __align__(16) float g_t[Bb][Hh][Cc];                // SCALE * (q . Wk)
__device__ float            g_ob[Bb][Hh];                      // SCALE * (q . bk)
__device__ __align__(16) float g_pu[SPLITS][Bb][Hh][Cc];       // partial sum_n w*x
__device__ float            g_pd[SPLITS][Bb][Hh];              // partial sum_n w
__device__ __align__(16) float g_clsp[12][Bb][Cc];             // cls partials
__device__ __align__(16) float g_outp[12][Bb][Cc];             // proj partials

// ---------------- helpers ----------------
typedef unsigned long long ull;
__device__ __forceinline__ void fma2(ull &d, ull a, ull b) {
    asm("fma.rn.f32x2 %0, %1, %2, %0;" : "+l"(d) : "l"(a), "l"(b));
}
__device__ __forceinline__ float hadd2(ull a) {
    unsigned int lo, hi;
    asm("mov.b64 {%0,%1}, %2;" : "=r"(lo), "=r"(hi) : "l"(a));
    return __uint_as_float(lo) + __uint_as_float(hi);
}
__device__ __forceinline__ ull dup2(float v) {
    ull r;
    asm("mov.b64 %0, {%1,%1};" : "=l"(r) : "r"(__float_as_uint(v)));
    return r;
}
__device__ __forceinline__ void cpa16(void* dst_smem, const void* src) {
    unsigned int d = (unsigned int)__cvta_generic_to_shared(dst_smem);
    asm volatile("cp.async.cg.shared.global [%0], [%1], 16;" :: "r"(d), "l"(src));
}

// ---------------- A1: q partials (k-split GEMM) ----------------
__global__ void k_qpart(const float* __restrict__ x, const float* __restrict__ qkv_w) {
    int jc = blockIdx.x, kc = blockIdx.y;
    __shared__ float xs[64][65];
    __shared__ float ws[64][65];
    int tid = threadIdx.x;
    for (int i = tid; i < 64 * 16; i += 256) {
        int r = i >> 4, c4 = (i & 15) * 4;
        float4 xv = *(const float4*)&x[(size_t)r * Nt * Cc + kc * 64 + c4];
        xs[r][c4] = xv.x; xs[r][c4 + 1] = xv.y; xs[r][c4 + 2] = xv.z; xs[r][c4 + 3] = xv.w;
        float4 wv = *(const float4*)&qkv_w[(size_t)(jc * 64 + r) * Cc + kc * 64 + c4];
        ws[r][c4] = wv.x; ws[r][c4 + 1] = wv.y; ws[r][c4 + 2] = wv.z; ws[r][c4 + 3] = wv.w;
    }
    __syncthreads();
    int ty = tid >> 4, tx = tid & 15;
    float acc[4][4] = {};
#pragma unroll 8
    for (int d = 0; d < 64; d++) {
        float a0 = xs[ty * 4 + 0][d], a1 = xs[ty * 4 + 1][d];
        float a2 = xs[ty * 4 + 2][d], a3 = xs[ty * 4 + 3][d];
        float b0 = ws[tx * 4 + 0][d], b1 = ws[tx * 4 + 1][d];
        float b2 = ws[tx * 4 + 2][d], b3 = ws[tx * 4 + 3][d];
        acc[0][0] += a0 * b0; acc[0][1] += a0 * b1; acc[0][2] += a0 * b2; acc[0][3] += a0 * b3;
        acc[1][0] += a1 * b0; acc[1][1] += a1 * b1; acc[1][2] += a1 * b2; acc[1][3] += a1 * b3;
        acc[2][0] += a2 * b0; acc[2][1] += a2 * b1; acc[2][2] += a2 * b2; acc[2][3] += a2 * b3;
        acc[3][0] += a3 * b0; acc[3][1] += a3 * b1; acc[3][2] += a3 * b2; acc[3][3] += a3 * b3;
    }
#pragma unroll
    for (int i = 0; i < 4; i++) {
        float4 v = make_float4(acc[i][0], acc[i][1], acc[i][2], acc[i][3]);
        *(float4*)&g_qpart[kc][ty * 4 + i][jc * 64 + tx * 4] = v;
    }
}

// ---------------- A2: t = SCALE*(q.Wk); ob  (q combined in-block from partials) ----------------
__global__ void k_t(const float* __restrict__ qkv_w, const float* __restrict__ qkv_b) {
    int h = blockIdx.x, cc2 = blockIdx.y;
    __shared__ float qs[64][65];
    __shared__ float wk[64][65];
    int tid = threadIdx.x;
    for (int i = tid; i < 64 * 16; i += 256) {
        int r = i >> 4, c4 = (i & 15) * 4;
        float4 s = *(const float4*)&qkv_b[h * 64 + c4];
#pragma unroll
        for (int kc = 0; kc < 12; kc++) {
            float4 p = *(const float4*)&g_qpart[kc][r][h * 64 + c4];
            s.x += p.x; s.y += p.y; s.z += p.z; s.w += p.w;
        }
        qs[r][c4] = s.x; qs[r][c4 + 1] = s.y; qs[r][c4 + 2] = s.z; qs[r][c4 + 3] = s.w;
        float4 wv = *(const float4*)&qkv_w[(size_t)(Cc + h * 64 + r) * Cc + cc2 * 64 + c4];
        wk[r][c4] = wv.x; wk[r][c4 + 1] = wv.y; wk[r][c4 + 2] = wv.z; wk[r][c4 + 3] = wv.w;
    }
    __syncthreads();
    int ty = tid >> 4, tx = tid & 15;
    float acc[4][4] = {};
#pragma unroll 8
    for (int d = 0; d < 64; d++) {
        float a0 = qs[ty * 4 + 0][d], a1 = qs[ty * 4 + 1][d];
        float a2 = qs[ty * 4 + 2][d], a3 = qs[ty * 4 + 3][d];
        float b0 = wk[d][tx * 4 + 0], b1 = wk[d][tx * 4 + 1];
        float b2 = wk[d][tx * 4 + 2], b3 = wk[d][tx * 4 + 3];
        acc[0][0] += a0 * b0; acc[0][1] += a0 * b1; acc[0][2] += a0 * b2; acc[0][3] += a0 * b3;
        acc[1][0] += a1 * b0; acc[1][1] += a1 * b1; acc[1][2] += a1 * b2; acc[1][3] += a1 * b3;
        acc[2][0] += a2 * b0; acc[2][1] += a2 * b1; acc[2][2] += a2 * b2; acc[2][3] += a2 * b3;
        acc[3][0] += a3 * b0; acc[3][1] += a3 * b1; acc[3][2] += a3 * b2; acc[3][3] += a3 * b3;
    }
#pragma unroll
    for (int i = 0; i < 4; i++) {
        float4 v = make_float4(SCv * acc[i][0], SCv * acc[i][1], SCv * acc[i][2], SCv * acc[i][3]);
        *(float4*)&g_t[ty * 4 + i][h][cc2 * 64 + tx * 4] = v;
    }
    if (cc2 == 0 && tid < 64) {
        float ssum = 0.f;
#pragma unroll 8
        for (int d = 0; d < 64; d++) ssum += qs[tid][d] * qkv_b[Cc + h * 64 + d];
        g_ob[tid][h] = SCv * ssum;
    }
}

// ---------------- B: main fused streaming kernel ----------------
// grid (64 b, 9 split), 384 thr.  warp = 64-ch slice; lane owns 3 heads x 8 ch.
// x kept in registers between logit phase and accumulate phase.
__global__ void __launch_bounds__(384, 2) k_attn(const float* __restrict__ x,
                                                 float* __restrict__ out) {
    int b = blockIdx.x, sp = blockIdx.y;
    int n0 = sp * CHUNK;
    int n1 = n0 + CHUNK; if (n1 > Nt) n1 = Nt;
    int ng = (n1 - n0 + G - 1) / G;
    int tid = threadIdx.x;
    int w = tid >> 5, l = tid & 31;
    int g3 = l >> 3;           // head triple 0..3
    int q = l & 7;             // channel octet within warp slice

    __shared__ __align__(16) float xb[3][G][Cc];     // triple-buffered token groups
    __shared__ float pl[G][12][13];                  // [token][warp][head] (+pad)
    __shared__ float wsm[G][12];
    __shared__ float obs[12];
    __shared__ float dsm[G * 12];

    int c1 = w * 64 + q * 8;                         // this lane's 8 channels
    int h0 = g3 * 3;                                 // this lane's first head

    // t slices: 3 heads x 8 ch, packed
    ull t1[3][4];
#pragma unroll
    for (int i = 0; i < 3; i++) {
        ulonglong2 p0 = *(const ulonglong2*)&g_t[b][h0 + i][c1];
        ulonglong2 p1 = *(const ulonglong2*)&g_t[b][h0 + i][c1 + 4];
        t1[i][0] = p0.x; t1[i][1] = p0.y; t1[i][2] = p1.x; t1[i][3] = p1.y;
    }
    if (tid < 12) obs[tid] = g_ob[b][tid];

    ull ua[3][4];
#pragma unroll
    for (int i = 0; i < 3; i++)
#pragma unroll
        for (int k = 0; k < 4; k++) ua[i][k] = 0ull;
    float dp = 0.f;

    const float* xrow = x + (size_t)b * Nt * Cc;

    // prologue: prefetch groups 0 and 1
#pragma unroll
    for (int g = 0; g < 2; g++) {
#pragma unroll
        for (int r = 0; r < 2; r++) {
            int idx = tid + r * 384;
            if (idx < 576) {
                int j = idx / 192, off = (idx % 192) * 4;
                int n = n0 + g * G + j;
                int nsrc = n < Nt ? n : Nt - 1;
                cpa16(&xb[g][j][off], xrow + (size_t)nsrc * Cc + off);
            }
        }
        asm volatile("cp.async.commit_group;");
    }

    for (int gi = 0; gi < ng; gi++) {
        int buf = gi % 3;
        int nbase = n0 + gi * G;
        asm volatile("cp.async.wait_group 1;");
        __syncthreads();                              // A: xb[buf] visible

        // ---- phase 1: logits; keep x in regs ----
        ull xv[G][4];
#pragma unroll
        for (int j = 0; j < G; j++) {
            ulonglong2 xp0 = *(const ulonglong2*)&xb[buf][j][c1];
            ulonglong2 xp1 = *(const ulonglong2*)&xb[buf][j][c1 + 4];
            xv[j][0] = xp0.x; xv[j][1] = xp0.y; xv[j][2] = xp1.x; xv[j][3] = xp1.y;
            float s[3];
#pragma unroll
            for (int i = 0; i < 3; i++) {
                ull a = 0ull;
                fma2(a, xv[j][0], t1[i][0]); fma2(a, xv[j][1], t1[i][1]);
                fma2(a, xv[j][2], t1[i][2]); fma2(a, xv[j][3], t1[i][3]);
                float sv = hadd2(a);
                sv += __shfl_xor_sync(0xffffffffu, sv, 4, 8);
                sv += __shfl_xor_sync(0xffffffffu, sv, 2, 8);
                sv += __shfl_xor_sync(0xffffffffu, sv, 1, 8);
                s[i] = sv;
            }
            if (q < 3) pl[j][w][h0 + q] = s[q];
        }
        __syncthreads();                              // B: pl published

        // prefetch group gi+2 into buffer (gi+2)%3 (== (gi-1)%3, free since p1(gi-1))
        {
            int gp = gi + 2;
#pragma unroll
            for (int r = 0; r < 2; r++) {
                int idx = tid + r * 384;
                if (gp < ng && idx < 576) {
                    int j = idx / 192, off = (idx % 192) * 4;
                    int n = n0 + gp * G + j;
                    int nsrc = n < Nt ? n : Nt - 1;
                    cpa16(&xb[gp % 3][j][off], xrow + (size_t)nsrc * Cc + off);
                }
            }
            asm volatile("cp.async.commit_group;");
        }

        // ---- combine (36 thr) overlapped with out-copy (g3==0 lanes) ----
        if (tid < G * 12) {
            int gg = tid / 12, h = tid % 12;
            int n = nbase + gg;
            float s = 0.f;
#pragma unroll
            for (int ww = 0; ww < 12; ww++) s += pl[gg][ww][h];
            float wv = (n < Nt) ? __expf(s + obs[h]) : 0.f;
            dp += wv;
            wsm[gg][h] = wv;
        }
        if (g3 == 0) {
#pragma unroll
            for (int j = 0; j < G; j++) {
                int n = nbase + j;
                if (n > 0 && n < Nt) {
                    ulonglong2 v0; v0.x = xv[j][0]; v0.y = xv[j][1];
                    ulonglong2 v1; v1.x = xv[j][2]; v1.y = xv[j][3];
                    size_t o = ((size_t)b * Nt + n) * Cc + c1;
                    *(ulonglong2*)&out[o] = v0;
                    *(ulonglong2*)&out[o + 4] = v1;
                }
            }
        }
        __syncthreads();                              // C: wsm ready

        // ---- phase 2: accumulate from registers ----
#pragma unroll
        for (int j = 0; j < G; j++) {
#pragma unroll
            for (int i = 0; i < 3; i++) {
                ull w2 = dup2(wsm[j][h0 + i]);
                fma2(ua[i][0], w2, xv[j][0]);
                fma2(ua[i][1], w2, xv[j][1]);
                fma2(ua[i][2], w2, xv[j][2]);
                fma2(ua[i][3], w2, xv[j][3]);
            }
        }
    }

    // epilogue: store split partials
#pragma unroll
    for (int i = 0; i < 3; i++) {
        ulonglong2 v0; v0.x = ua[i][0]; v0.y = ua[i][1];
        ulonglong2 v1; v1.x = ua[i][2]; v1.y = ua[i][3];
        *(ulonglong2*)&g_pu[sp][b][h0 + i][c1] = v0;
        *(ulonglong2*)&g_pu[sp][b][h0 + i][c1 + 4] = v1;
    }
    if (tid < G * 12) dsm[tid] = dp;
    __syncthreads();
    if (tid < 12) {
        float s = 0.f;
#pragma unroll
        for (int gg = 0; gg < G; gg++) s += dsm[gg * 12 + tid];
        g_pd[sp][b][tid] = s;
    }
}

// ---------------- C1: cls partials (fused split-combine + normalize) ----------------
__global__ void k_cls(const float* __restrict__ qkv_w) {
    int h = blockIdx.x, kc = blockIdx.y;
    __shared__ float us[64][65];
    __shared__ float wv[64][65];
    __shared__ float dsh[64];
    int tid = threadIdx.x;
    if (tid < 64) {
        float s = 0.f;
#pragma unroll
        for (int sp = 0; sp < SPLITS; sp++) s += g_pd[sp][tid][h];
        dsh[tid] = 1.f / s;
    }
    __syncthreads();
    for (int i = tid; i < 64 * 16; i += 256) {
        int r = i >> 4, c4 = (i & 15) * 4;
        float4 acc = make_float4(0.f, 0.f, 0.f, 0.f);
#pragma unroll
        for (int sp = 0; sp < SPLITS; sp++) {
            float4 p = *(const float4*)&g_pu[sp][r][h][kc * 64 + c4];
            acc.x += p.x; acc.y += p.y; acc.z += p.z; acc.w += p.w;
        }
        float inv = dsh[r];
        us[r][c4] = acc.x * inv; us[r][c4 + 1] = acc.y * inv;
        us[r][c4 + 2] = acc.z * inv; us[r][c4 + 3] = acc.w * inv;
        float4 wvv = *(const float4*)&qkv_w[(size_t)(2 * Cc + h * 64 + r) * Cc + kc * 64 + c4];
        wv[r][c4] = wvv.x; wv[r][c4 + 1] = wvv.y; wv[r][c4 + 2] = wvv.z; wv[r][c4 + 3] = wvv.w;
    }
    __syncthreads();
    int ty = tid >> 4, tx = tid & 15;
    float acc[4][4] = {};
#pragma unroll 8
    for (int c = 0; c < 64; c++) {
        float a0 = us[ty * 4 + 0][c], a1 = us[ty * 4 + 1][c];
        float a2 = us[ty * 4 + 2][c], a3 = us[ty * 4 + 3][c];
        float b0 = wv[tx * 4 + 0][c], b1 = wv[tx * 4 + 1][c];
        float b2 = wv[tx * 4 + 2][c], b3 = wv[tx * 4 + 3][c];
        acc[0][0] += a0 * b0; acc[0][1] += a0 * b1; acc[0][2] += a0 * b2; acc[0][3] += a0 * b3;
        acc[1][0] += a1 * b0; acc[1][1] += a1 * b1; acc[1][2] += a1 * b2; acc[1][3] += a1 * b3;
        acc[2][0] += a2 * b0; acc[2][1] += a2 * b1; acc[2][2] += a2 * b2; acc[2][3] += a2 * b3;
        acc[3][0] += a3 * b0; acc[3][1] += a3 * b1; acc[3][2] += a3 * b2; acc[3][3] += a3 * b3;
    }
#pragma unroll
    for (int i = 0; i < 4; i++) {
        float4 v = make_float4(acc[i][0], acc[i][1], acc[i][2], acc[i][3]);
        *(float4*)&g_clsp[kc][ty * 4 + i][h * 64 + tx * 4] = v;
    }
}

// ---------------- C2: proj partials ----------------
__global__ void k_proj(const float* __restrict__ qkv_b, const float* __restrict__ proj_w) {
    int jc = blockIdx.x, kc = blockIdx.y;
    __shared__ float cs[64][65];
    __shared__ float pw[64][65];
    int tid = threadIdx.x;
    for (int i = tid; i < 64 * 16; i += 256) {
        int r = i >> 4, c4 = (i & 15) * 4;
        float4 s = *(const float4*)&qkv_b[2 * Cc + kc * 64 + c4];
#pragma unroll
        for (int p = 0; p < 12; p++) {
            float4 pv = *(const float4*)&g_clsp[p][r][kc * 64 + c4];
            s.x += pv.x; s.y += pv.y; s.z += pv.z; s.w += pv.w;
        }
        cs[r][c4] = s.x; cs[r][c4 + 1] = s.y; cs[r][c4 + 2] = s.z; cs[r][c4 + 3] = s.w;
        float4 wv = *(const float4*)&proj_w[(size_t)(jc * 64 + r) * Cc + kc * 64 + c4];
        pw[r][c4] = wv.x; pw[r][c4 + 1] = wv.y; pw[r][c4 + 2] = wv.z; pw[r][c4 + 3] = wv.w;
    }
    __syncthreads();
    int ty = tid >> 4, tx = tid & 15;
    float acc[4][4] = {};
#pragma unroll 8
    for (int c = 0; c < 64; c++) {
        float a0 = cs[ty * 4 + 0][c], a1 = cs[ty * 4 + 1][c];
        float a2 = cs[ty * 4 + 2][c], a3 = cs[ty * 4 + 3][c];
        float b0 = pw[tx * 4 + 0][c], b1 = pw[tx * 4 + 1][c];
        float b2 = pw[tx * 4 + 2][c], b3 = pw[tx * 4 + 3][c];
        acc[0][0] += a0 * b0; acc[0][1] += a0 * b1; acc[0][2] += a0 * b2; acc[0][3] += a0 * b3;
        acc[1][0] += a1 * b0; acc[1][1] += a1 * b1; acc[1][2] += a1 * b2; acc[1][3] += a1 * b3;
        acc[2][0] += a2 * b0; acc[2][1] += a2 * b1; acc[2][2] += a2 * b2; acc[2][3] += a2 * b3;
        acc[3][0] += a3 * b0; acc[3][1] += a3 * b1; acc[3][2] += a3 * b2; acc[3][3] += a3 * b3;
    }
#pragma unroll
    for (int i = 0; i < 4; i++) {
        float4 v = make_float4(acc[i][0], acc[i][1], acc[i][2], acc[i][3]);
        *(float4*)&g_outp[kc][ty * 4 + i][jc * 64 + tx * 4] = v;
    }
}

// ---------------- C3: combine proj partials + proj_b -> out[:,0,:] ----------------
__global__ void k_final(const float* __restrict__ proj_b, float* __restrict__ out) {
    int idx = blockIdx.x * 256 + threadIdx.x;
    if (idx >= Bb * Cc / 4) return;
    int b = idx / 192, j4 = (idx % 192) * 4;
    float4 s = *(const float4*)&proj_b[j4];
#pragma unroll
    for (int p = 0; p < 12; p++) {
        float4 pv = *(const float4*)&g_outp[p][b][j4];
        s.x += pv.x; s.y += pv.y; s.z += pv.z; s.w += pv.w;
    }
    *(float4*)&out[(size_t)b * Nt * Cc + j4] = s;
}

// ---------------- launch ----------------
extern "C" void kernel_launch(void* const* d_in, const int* in_sizes, int n_in,
                              void* d_out, int out_size) {
    (void)in_sizes; (void)n_in; (void)out_size;
    const float* x      = (const float*)d_in[0];
    const float* qkv_w  = (const float*)d_in[1];
    const float* qkv_b  = (const float*)d_in[2];
    const float* proj_w = (const float*)d_in[3];
    const float* proj_b = (const float*)d_in[4];
    float* out = (float*)d_out;

    k_qpart<<<dim3(12, 12), 256>>>(x, qkv_w);
    k_t    <<<dim3(12, 12), 256>>>(qkv_w, qkv_b);
    k_attn <<<dim3(64, SPLITS), 384>>>(x, out);
    k_cls  <<<dim3(12, 12), 256>>>(qkv_w);
    k_proj <<<dim3(12, 12), 256>>>(qkv_b, proj_w);
    k_final<<<48, 256>>>(proj_b, out);
}

// round 6
// speedup vs baseline: 1.2917x; 1.2917x over previous
#include <cuda_runtime.h>
#include <cstdint>
#include <cstddef>

// Problem constants
#define Bb 64
#define Nt 577
#define Cc 768
#define Hh 12
#define SCv 0.125f
#define SPLITS 9
#define CHUNK 65        // ceil(577/9)
#define G 6             // tokens per group in k_attn

// ---------------- scratch (device globals; no allocation) ----------------
__device__ __align__(16) float g_qpart[12][Bb][Cc];            // q partial sums (kc,b,j)
__device__ __align__(16) float g_t[Bb][Hh][Cc];                // SCALE * (q . Wk)
__device__ float            g_ob[Bb][Hh];                      // SCALE * (q . bk)
__device__ __align__(16) float g_pu[SPLITS][Bb][Hh][Cc];       // partial sum_n w*x
__device__ float            g_pd[SPLITS][Bb][Hh];              // partial sum_n w
__device__ __align__(16) float g_ubar[Bb][Hh][Cc];             // normalized u
__device__ __align__(16) float g_clsp[12][Bb][Cc];             // cls partials
__device__ __align__(16) float g_outp[12][Bb][Cc];             // proj partials

// ---------------- helpers ----------------
typedef unsigned long long ull;
__device__ __forceinline__ void fma2(ull &d, ull a, ull b) {
    asm("fma.rn.f32x2 %0, %1, %2, %0;" : "+l"(d) : "l"(a), "l"(b));
}
__device__ __forceinline__ float hadd2(ull a) {
    unsigned int lo, hi;
    asm("mov.b64 {%0,%1}, %2;" : "=r"(lo), "=r"(hi) : "l"(a));
    return __uint_as_float(lo) + __uint_as_float(hi);
}
__device__ __forceinline__ ull dup2(float v) {
    ull r;
    asm("mov.b64 %0, {%1,%1};" : "=l"(r) : "r"(__float_as_uint(v)));
    return r;
}
__device__ __forceinline__ void cpa16(void* dst_smem, const void* src) {
    unsigned int d = (unsigned int)__cvta_generic_to_shared(dst_smem);
    asm volatile("cp.async.cg.shared.global [%0], [%1], 16;" :: "r"(d), "l"(src));
}

// ---------------- A1: q partials (k-split GEMM) ----------------
__global__ void k_qpart(const float* __restrict__ x, const float* __restrict__ qkv_w) {
    int jc = blockIdx.x, kc = blockIdx.y;
    __shared__ float xs[64][65];
    __shared__ float ws[64][65];
    int tid = threadIdx.x;
    for (int i = tid; i < 64 * 16; i += 256) {
        int r = i >> 4, c4 = (i & 15) * 4;
        float4 xv = *(const float4*)&x[(size_t)r * Nt * Cc + kc * 64 + c4];
        xs[r][c4] = xv.x; xs[r][c4 + 1] = xv.y; xs[r][c4 + 2] = xv.z; xs[r][c4 + 3] = xv.w;
        float4 wv = *(const float4*)&qkv_w[(size_t)(jc * 64 + r) * Cc + kc * 64 + c4];
        ws[r][c4] = wv.x; ws[r][c4 + 1] = wv.y; ws[r][c4 + 2] = wv.z; ws[r][c4 + 3] = wv.w;
    }
    __syncthreads();
    int ty = tid >> 4, tx = tid & 15;
    float acc[4][4] = {};
#pragma unroll 8
    for (int d = 0; d < 64; d++) {
        float a0 = xs[ty * 4 + 0][d], a1 = xs[ty * 4 + 1][d];
        float a2 = xs[ty * 4 + 2][d], a3 = xs[ty * 4 + 3][d];
        float b0 = ws[tx * 4 + 0][d], b1 = ws[tx * 4 + 1][d];
        float b2 = ws[tx * 4 + 2][d], b3 = ws[tx * 4 + 3][d];
        acc[0][0] += a0 * b0; acc[0][1] += a0 * b1; acc[0][2] += a0 * b2; acc[0][3] += a0 * b3;
        acc[1][0] += a1 * b0; acc[1][1] += a1 * b1; acc[1][2] += a1 * b2; acc[1][3] += a1 * b3;
        acc[2][0] += a2 * b0; acc[2][1] += a2 * b1; acc[2][2] += a2 * b2; acc[2][3] += a2 * b3;
        acc[3][0] += a3 * b0; acc[3][1] += a3 * b1; acc[3][2] += a3 * b2; acc[3][3] += a3 * b3;
    }
#pragma unroll
    for (int i = 0; i < 4; i++) {
        float4 v = make_float4(acc[i][0], acc[i][1], acc[i][2], acc[i][3]);
        *(float4*)&g_qpart[kc][ty * 4 + i][jc * 64 + tx * 4] = v;
    }
}

// ---------------- A2: t = SCALE*(q.Wk); ob  (q combined in-block) ----------------
__global__ void k_t(const float* __restrict__ qkv_w, const float* __restrict__ qkv_b) {
    int h = blockIdx.x, cc2 = blockIdx.y;
    __shared__ float qs[64][65];
    __shared__ float wk[64][65];
    int tid = threadIdx.x;
    for (int i = tid; i < 64 * 16; i += 256) {
        int r = i >> 4, c4 = (i & 15) * 4;
        float4 s = *(const float4*)&qkv_b[h * 64 + c4];
#pragma unroll
        for (int kc = 0; kc < 12; kc++) {
            float4 p = *(const float4*)&g_qpart[kc][r][h * 64 + c4];
            s.x += p.x; s.y += p.y; s.z += p.z; s.w += p.w;
        }
        qs[r][c4] = s.x; qs[r][c4 + 1] = s.y; qs[r][c4 + 2] = s.z; qs[r][c4 + 3] = s.w;
        float4 wv = *(const float4*)&qkv_w[(size_t)(Cc + h * 64 + r) * Cc + cc2 * 64 + c4];
        wk[r][c4] = wv.x; wk[r][c4 + 1] = wv.y; wk[r][c4 + 2] = wv.z; wk[r][c4 + 3] = wv.w;
    }
    __syncthreads();
    int ty = tid >> 4, tx = tid & 15;
    float acc[4][4] = {};
#pragma unroll 8
    for (int d = 0; d < 64; d++) {
        float a0 = qs[ty * 4 + 0][d], a1 = qs[ty * 4 + 1][d];
        float a2 = qs[ty * 4 + 2][d], a3 = qs[ty * 4 + 3][d];
        float b0 = wk[d][tx * 4 + 0], b1 = wk[d][tx * 4 + 1];
        float b2 = wk[d][tx * 4 + 2], b3 = wk[d][tx * 4 + 3];
        acc[0][0] += a0 * b0; acc[0][1] += a0 * b1; acc[0][2] += a0 * b2; acc[0][3] += a0 * b3;
        acc[1][0] += a1 * b0; acc[1][1] += a1 * b1; acc[1][2] += a1 * b2; acc[1][3] += a1 * b3;
        acc[2][0] += a2 * b0; acc[2][1] += a2 * b1; acc[2][2] += a2 * b2; acc[2][3] += a2 * b3;
        acc[3][0] += a3 * b0; acc[3][1] += a3 * b1; acc[3][2] += a3 * b2; acc[3][3] += a3 * b3;
    }
#pragma unroll
    for (int i = 0; i < 4; i++) {
        float4 v = make_float4(SCv * acc[i][0], SCv * acc[i][1], SCv * acc[i][2], SCv * acc[i][3]);
        *(float4*)&g_t[ty * 4 + i][h][cc2 * 64 + tx * 4] = v;
    }
    if (cc2 == 0 && tid < 64) {
        float ssum = 0.f;
#pragma unroll 8
        for (int d = 0; d < 64; d++) ssum += qs[tid][d] * qkv_b[Cc + h * 64 + d];
        g_ob[tid][h] = SCv * ssum;
    }
}

// ---------------- B: main fused streaming kernel (R3 structure) ----------------
// grid (64 b, 9 split), 384 thr.  warp = 64-channel slice.
// Phase 1: lane-groups of 8, 3 heads each, shfl width=8 reductions.
// Phase 2: 2 channels/lane, packed f32x2 accumulate with pre-packed weights.
__global__ void __launch_bounds__(384, 2) k_attn(const float* __restrict__ x,
                                                 float* __restrict__ out) {
    int b = blockIdx.x, sp = blockIdx.y;
    int n0 = sp * CHUNK;
    int n1 = n0 + CHUNK; if (n1 > Nt) n1 = Nt;
    int ng = (n1 - n0 + G - 1) / G;
    int tid = threadIdx.x;
    int w = tid >> 5, l = tid & 31;
    int g3 = l >> 3;           // lane group 0..3 -> heads 3*g3..3*g3+2
    int q = l & 7;             // lane in group

    __shared__ __align__(16) float xb[2][G][Cc];
    __shared__ float pl[G][12][13];                  // [token][warp][head] (+pad)
    __shared__ ull  wsm2[G][12];                     // pre-packed {w,w}
    __shared__ float obs[12];
    __shared__ float dsm[G * 12];

    // phase-1 t: heads 3g3..3g3+2, channels w*64 + q*8 .. +7, packed
    int c1 = w * 64 + q * 8;
    ull t1[3][4];
#pragma unroll
    for (int i = 0; i < 3; i++) {
        ulonglong2 p0 = *(const ulonglong2*)&g_t[b][g3 * 3 + i][c1];
        ulonglong2 p1 = *(const ulonglong2*)&g_t[b][g3 * 3 + i][c1 + 4];
        t1[i][0] = p0.x; t1[i][1] = p0.y; t1[i][2] = p1.x; t1[i][3] = p1.y;
    }
    if (tid < 12) obs[tid] = g_ob[b][tid];

    // phase-2 accumulators: 2 channels per lane, all 12 heads, packed
    int c2 = w * 64 + l * 2;
    ull ua[12];
#pragma unroll
    for (int h = 0; h < 12; h++) ua[h] = 0ull;
    float dp = 0.f;

    const float* xrow = x + (size_t)b * Nt * Cc;
    __syncthreads();

    // prologue: load group 0
#pragma unroll
    for (int r = 0; r < 3; r++) {
        int i = tid + r * 384;
        int j = i / 192, off = (i % 192) * 4;
        int n = n0 + j;
        if (n < n1) cpa16(&xb[0][j][off], xrow + (size_t)n * Cc + off);
    }
    asm volatile("cp.async.commit_group;");

    for (int gi = 0; gi < ng; gi++) {
        int buf = gi & 1;
        int nbase = n0 + gi * G;
        // prefetch next group
        {
            int nb2 = nbase + G;
#pragma unroll
            for (int r = 0; r < 3; r++) {
                int i = tid + r * 384;
                int j = i / 192, off = (i % 192) * 4;
                int n = nb2 + j;
                if (gi + 1 < ng && n < n1) cpa16(&xb[buf ^ 1][j][off], xrow + (size_t)n * Cc + off);
            }
            asm volatile("cp.async.commit_group;");
        }
        asm volatile("cp.async.wait_group 1;");
        __syncthreads();

        // ---- phase 1: logits ----
#pragma unroll
        for (int j = 0; j < G; j++) {
            int n = nbase + j;
            if (n >= n1) break;
            ulonglong2 xp0 = *(const ulonglong2*)&xb[buf][j][c1];
            ulonglong2 xp1 = *(const ulonglong2*)&xb[buf][j][c1 + 4];
            ull xv0 = xp0.x, xv1 = xp0.y, xv2 = xp1.x, xv3 = xp1.y;
            float s[3];
#pragma unroll
            for (int i = 0; i < 3; i++) {
                ull a = 0ull;
                fma2(a, xv0, t1[i][0]); fma2(a, xv1, t1[i][1]);
                fma2(a, xv2, t1[i][2]); fma2(a, xv3, t1[i][3]);
                float sv = hadd2(a);
                sv += __shfl_xor_sync(0xffffffffu, sv, 4, 8);
                sv += __shfl_xor_sync(0xffffffffu, sv, 2, 8);
                sv += __shfl_xor_sync(0xffffffffu, sv, 1, 8);
                s[i] = sv;
            }
            if (q < 3) pl[j][w][g3 * 3 + q] = s[q];
        }
        __syncthreads();

        // ---- combine: 72 threads -> packed weights ----
        if (tid < G * 12) {
            int gg = tid / 12, h = tid % 12;
            int n = nbase + gg;
            float s = 0.f;
#pragma unroll
            for (int ww = 0; ww < 12; ww++) s += pl[gg][ww][h];
            float wv = 0.f;
            if (n < n1) wv = __expf(s + obs[h]);
            dp += wv;
            wsm2[gg][h] = dup2(wv);
        }
        __syncthreads();

        // ---- phase 2: accumulate + copy out ----
#pragma unroll
        for (int j = 0; j < G; j++) {
            int n = nbase + j;
            if (n >= n1) break;
            ull xv = *(const ull*)&xb[buf][j][c2];
#pragma unroll
            for (int h = 0; h < 12; h++)
                fma2(ua[h], wsm2[j][h], xv);
            if (n > 0)
                *(ull*)&out[((size_t)b * Nt + n) * Cc + c2] = xv;
        }
        __syncthreads();
    }

    // store split partials
#pragma unroll
    for (int h = 0; h < 12; h++)
        *(ull*)&g_pu[sp][b][h][c2] = ua[h];
    if (tid < G * 12) dsm[tid] = dp;
    __syncthreads();
    if (tid < 12) {
        float s = 0.f;
#pragma unroll
        for (int gg = 0; gg < G; gg++) s += dsm[gg * 12 + tid];
        g_pd[sp][b][tid] = s;
    }
}

// ---------------- B2: wide combine of u partials -> normalized ubar ----------------
__global__ void k_ured(void) {
    int idx = blockIdx.x * 256 + threadIdx.x;
    if (idx >= Bb * Hh * Cc / 4) return;
    int c4 = (idx % 192) * 4;
    int h = (idx / 192) % Hh;
    int b = idx / (192 * Hh);
    float d = 0.f;
#pragma unroll
    for (int s = 0; s < SPLITS; s++) d += g_pd[s][b][h];
    float4 acc = make_float4(0.f, 0.f, 0.f, 0.f);
#pragma unroll
    for (int s = 0; s < SPLITS; s++) {
        float4 p = *(const float4*)&g_pu[s][b][h][c4];
        acc.x += p.x; acc.y += p.y; acc.z += p.z; acc.w += p.w;
    }
    float inv = 1.f / d;
    acc.x *= inv; acc.y *= inv; acc.z *= inv; acc.w *= inv;
    *(float4*)&g_ubar[b][h][c4] = acc;
}

// ---------------- C1: cls partials ----------------
__global__ void k_cls(const float* __restrict__ qkv_w) {
    int h = blockIdx.x, kc = blockIdx.y;
    __shared__ float us[64][65];
    __shared__ float wv[64][65];
    int tid = threadIdx.x;
    for (int i = tid; i < 64 * 16; i += 256) {
        int r = i >> 4, c4 = (i & 15) * 4;
        float4 uv = *(const float4*)&g_ubar[r][h][kc * 64 + c4];
        us[r][c4] = uv.x; us[r][c4 + 1] = uv.y; us[r][c4 + 2] = uv.z; us[r][c4 + 3] = uv.w;
        float4 wvv = *(const float4*)&qkv_w[(size_t)(2 * Cc + h * 64 + r) * Cc + kc * 64 + c4];
        wv[r][c4] = wvv.x; wv[r][c4 + 1] = wvv.y; wv[r][c4 + 2] = wvv.z; wv[r][c4 + 3] = wvv.w;
    }
    __syncthreads();
    int ty = tid >> 4, tx = tid & 15;
    float acc[4][4] = {};
#pragma unroll 8
    for (int c = 0; c < 64; c++) {
        float a0 = us[ty * 4 + 0][c], a1 = us[ty * 4 + 1][c];
        float a2 = us[ty * 4 + 2][c], a3 = us[ty * 4 + 3][c];
        float b0 = wv[tx * 4 + 0][c], b1 = wv[tx * 4 + 1][c];
        float b2 = wv[tx * 4 + 2][c], b3 = wv[tx * 4 + 3][c];
        acc[0][0] += a0 * b0; acc[0][1] += a0 * b1; acc[0][2] += a0 * b2; acc[0][3] += a0 * b3;
        acc[1][0] += a1 * b0; acc[1][1] += a1 * b1; acc[1][2] += a1 * b2; acc[1][3] += a1 * b3;
        acc[2][0] += a2 * b0; acc[2][1] += a2 * b1; acc[2][2] += a2 * b2; acc[2][3] += a2 * b3;
        acc[3][0] += a3 * b0; acc[3][1] += a3 * b1; acc[3][2] += a3 * b2; acc[3][3] += a3 * b3;
    }
#pragma unroll
    for (int i = 0; i < 4; i++) {
        float4 v = make_float4(acc[i][0], acc[i][1], acc[i][2], acc[i][3]);
        *(float4*)&g_clsp[kc][ty * 4 + i][h * 64 + tx * 4] = v;
    }
}

// ---------------- C2: proj partials ----------------
__global__ void k_proj(const float* __restrict__ qkv_b, const float* __restrict__ proj_w) {
    int jc = blockIdx.x, kc = blockIdx.y;
    __shared__ float cs[64][65];
    __shared__ float pw[64][65];
    int tid = threadIdx.x;
    for (int i = tid; i < 64 * 16; i += 256) {
        int r = i >> 4, c4 = (i & 15) * 4;
        float4 s = *(const float4*)&qkv_b[2 * Cc + kc * 64 + c4];
#pragma unroll
        for (int p = 0; p < 12; p++) {
            float4 pv = *(const float4*)&g_clsp[p][r][kc * 64 + c4];
            s.x += pv.x; s.y += pv.y; s.z += pv.z; s.w += pv.w;
        }
        cs[r][c4] = s.x; cs[r][c4 + 1] = s.y; cs[r][c4 + 2] = s.z; cs[r][c4 + 3] = s.w;
        float4 wv = *(const float4*)&proj_w[(size_t)(jc * 64 + r) * Cc + kc * 64 + c4];
        pw[r][c4] = wv.x; pw[r][c4 + 1] = wv.y; pw[r][c4 + 2] = wv.z; pw[r][c4 + 3] = wv.w;
    }
    __syncthreads();
    int ty = tid >> 4, tx = tid & 15;
    float acc[4][4] = {};
#pragma unroll 8
    for (int c = 0; c < 64; c++) {
        float a0 = cs[ty * 4 + 0][c], a1 = cs[ty * 4 + 1][c];
        float a2 = cs[ty * 4 + 2][c], a3 = cs[ty * 4 + 3][c];
        float b0 = pw[tx * 4 + 0][c], b1 = pw[tx * 4 + 1][c];
        float b2 = pw[tx * 4 + 2][c], b3 = pw[tx * 4 + 3][c];
        acc[0][0] += a0 * b0; acc[0][1] += a0 * b1; acc[0][2] += a0 * b2; acc[0][3] += a0 * b3;
        acc[1][0] += a1 * b0; acc[1][1] += a1 * b1; acc[1][2] += a1 * b2; acc[1][3] += a1 * b3;
        acc[2][0] += a2 * b0; acc[2][1] += a2 * b1; acc[2][2] += a2 * b2; acc[2][3] += a2 * b3;
        acc[3][0] += a3 * b0; acc[3][1] += a3 * b1; acc[3][2] += a3 * b2; acc[3][3] += a3 * b3;
    }
#pragma unroll
    for (int i = 0; i < 4; i++) {
        float4 v = make_float4(acc[i][0], acc[i][1], acc[i][2], acc[i][3]);
        *(float4*)&g_outp[kc][ty * 4 + i][jc * 64 + tx * 4] = v;
    }
}

// ---------------- C3: combine proj partials + proj_b -> out[:,0,:] ----------------
__global__ void k_final(const float* __restrict__ proj_b, float* __restrict__ out) {
    int idx = blockIdx.x * 256 + threadIdx.x;
    if (idx >= Bb * Cc / 4) return;
    int b = idx / 192, j4 = (idx % 192) * 4;
    float4 s = *(const float4*)&proj_b[j4];
#pragma unroll
    for (int p = 0; p < 12; p++) {
        float4 pv = *(const float4*)&g_outp[p][b][j4];
        s.x += pv.x; s.y += pv.y; s.z += pv.z; s.w += pv.w;
    }
    *(float4*)&out[(size_t)b * Nt * Cc + j4] = s;
}

// ---------------- launch ----------------
extern "C" void kernel_launch(void* const* d_in, const int* in_sizes, int n_in,
                              void* d_out, int out_size) {
    (void)in_sizes; (void)n_in; (void)out_size;
    const float* x      = (const float*)d_in[0];
    const float* qkv_w  = (const float*)d_in[1];
    const float* qkv_b  = (const float*)d_in[2];
    const float* proj_w = (const float*)d_in[3];
    const float* proj_b = (const float*)d_in[4];
    float* out = (float*)d_out;

    k_qpart<<<dim3(12, 12), 256>>>(x, qkv_w);
    k_t    <<<dim3(12, 12), 256>>>(qkv_w, qkv_b);
    k_attn <<<dim3(64, SPLITS), 384>>>(x, out);
    k_ured <<<576, 256>>>();
    k_cls  <<<dim3(12, 12), 256>>>(qkv_w);
    k_proj <<<dim3(12, 12), 256>>>(qkv_b, proj_w);
    k_final<<<48, 256>>>(proj_b, out);
}